// round 2
// baseline (speedup 1.0000x reference)
#include <cuda_runtime.h>
#include <cuda_bf16.h>
#include <cstdint>

// Problem dims (fixed by the dataset)
#define M_DIM 4096   // B*S tokens
#define N_DIM 4096   // OUT
#define K_DIM 4096   // IN
#define RANK 8
#define LORA_R 16
#define LORA_SCALING_C 1.0f  // 16.0/16

#define TILE_M 128
#define TILE_N 128
#define KCHUNK 32                  // fp32 K elements per stage (hi+lo packed = 128B/row)
#define NCHUNKS (K_DIM / KCHUNK)   // 128
#define NSTAGES 4
#define STAGE_BYTES 32768          // 16KB A + 16KB B
#define SMEM_TOTAL (NSTAGES * STAGE_BYTES)   // 131072

// Packed hi/lo bf16 scratch: per (row, kc): 64 bf16 = [32 hi | 32 lo] = 128 bytes
__device__ __align__(128) __nv_bfloat16 g_xpk[(size_t)M_DIM * K_DIM * 2];
__device__ __align__(128) __nv_bfloat16 g_wpk[(size_t)N_DIM * K_DIM * 2];

// ---------------- PTX helpers (sm_103 baseline ISA only) ----------------

__device__ __forceinline__ uint32_t smem_u32(const void* p) {
    uint32_t a;
    asm("{ .reg .u64 t; cvta.to.shared.u64 t, %1; cvt.u32.u64 %0, t; }"
        : "=r"(a) : "l"(p));
    return a;
}

__device__ __forceinline__ void ldsm4(uint32_t* r, uint32_t addr) {
    asm volatile("ldmatrix.sync.aligned.m8n8.x4.shared.b16 {%0,%1,%2,%3}, [%4];"
                 : "=r"(r[0]), "=r"(r[1]), "=r"(r[2]), "=r"(r[3]) : "r"(addr));
}

__device__ __forceinline__ void mma16816(float* c, const uint32_t* a,
                                         const uint32_t* b) {
    asm volatile(
        "mma.sync.aligned.m16n8k16.row.col.f32.bf16.bf16.f32 "
        "{%0,%1,%2,%3}, {%4,%5,%6,%7}, {%8,%9}, {%0,%1,%2,%3};"
        : "+f"(c[0]), "+f"(c[1]), "+f"(c[2]), "+f"(c[3])
        : "r"(a[0]), "r"(a[1]), "r"(a[2]), "r"(a[3]), "r"(b[0]), "r"(b[1]));
}

__device__ __forceinline__ void cp_async16(uint32_t dst, const void* src) {
    asm volatile("cp.async.cg.shared.global [%0], [%1], 16;"
                 :: "r"(dst), "l"(src));
}
#define CP_COMMIT() asm volatile("cp.async.commit_group;" ::: "memory")
#define CP_WAIT2()  asm volatile("cp.async.wait_group 2;" ::: "memory")

// ---------------- Precompute kernels ----------------

__global__ void precomp_x(const float* __restrict__ x) {
    int idx = blockIdx.x * 256 + threadIdx.x;   // < 16777216
    float v = x[idx];
    __nv_bfloat16 hi = __float2bfloat16(v);
    __nv_bfloat16 lo = __float2bfloat16(v - __bfloat162float(hi));
    int m = idx >> 12;
    int k = idx & 4095;
    size_t base = ((size_t)m * 128 + (k >> 5)) * 64 + (k & 31);
    g_xpk[base] = hi;
    g_xpk[base + 32] = lo;
}

// W_tot[o][i] = weight[o][i] * sum_k (scale_A[o][k]*g[k]) * scale_B[k][i]
//            + scaling * sum_r lora_B[o][r] * lora_A[r][i]
__global__ void precomp_w(const float* __restrict__ weight,
                          const float* __restrict__ scale_A,
                          const float* __restrict__ scale_B,
                          const float* __restrict__ g,
                          const float* __restrict__ lora_A,
                          const float* __restrict__ lora_B) {
    __shared__ float ag[64][8];
    __shared__ float lb[64][16];
    int t = threadIdx.x;
    int i0 = blockIdx.x * 256;
    int o0 = blockIdx.y * 64;

    for (int u = t; u < 64 * 8; u += 256) {
        int ol = u >> 3, k = u & 7;
        ag[ol][k] = scale_A[(size_t)(o0 + ol) * RANK + k] * g[k];
    }
    for (int u = t; u < 64 * 16; u += 256) {
        int ol = u >> 4, r = u & 15;
        lb[ol][r] = lora_B[(size_t)(o0 + ol) * LORA_R + r] * LORA_SCALING_C;
    }
    __syncthreads();

    int i = i0 + t;
    float sb[8], la[16];
#pragma unroll
    for (int k = 0; k < 8; k++) sb[k] = scale_B[(size_t)k * K_DIM + i];
#pragma unroll
    for (int r = 0; r < 16; r++) la[r] = lora_A[(size_t)r * K_DIM + i];

    int kc = i >> 5;
    int j = i & 31;
#pragma unroll 4
    for (int ol = 0; ol < 64; ol++) {
        int o = o0 + ol;
        float S = 0.0f, L = 0.0f;
#pragma unroll
        for (int k = 0; k < 8; k++) S = fmaf(ag[ol][k], sb[k], S);
#pragma unroll
        for (int r = 0; r < 16; r++) L = fmaf(lb[ol][r], la[r], L);
        float w = weight[(size_t)o * K_DIM + i];
        float tot = fmaf(w, S, L);
        __nv_bfloat16 hi = __float2bfloat16(tot);
        __nv_bfloat16 lo = __float2bfloat16(tot - __bfloat162float(hi));
        size_t base = ((size_t)o * 128 + kc) * 64 + j;
        g_wpk[base] = hi;
        g_wpk[base + 32] = lo;
    }
}

// ---------------- GEMM kernel (mma.sync HMMA, bf16x3) ----------------

__device__ __forceinline__ void issue_stage(uint32_t sb, int tid, int m0, int n0,
                                            int chunk, int stage) {
    uint32_t sA = sb + stage * STAGE_BYTES;
    uint32_t sB = sA + 16384;
    const char* xg = reinterpret_cast<const char*>(g_xpk);
    const char* wg = reinterpret_cast<const char*>(g_wpk);
#pragma unroll
    for (int p = 0; p < 4; p++) {
        int v = tid + p * 256;
        int row = v >> 3, c = v & 7;
        uint32_t dst = sA + (uint32_t)(row * 128 + ((c * 16) ^ ((row & 7) << 4)));
        const char* src = xg + (((size_t)(m0 + row) * 128 + chunk) * 128 + c * 16);
        cp_async16(dst, src);
    }
#pragma unroll
    for (int p = 0; p < 4; p++) {
        int v = tid + p * 256;
        int row = v >> 3, c = v & 7;
        uint32_t dst = sB + (uint32_t)(row * 128 + ((c * 16) ^ ((row & 7) << 4)));
        const char* src = wg + (((size_t)(n0 + row) * 128 + chunk) * 128 + c * 16);
        cp_async16(dst, src);
    }
}

__global__ void __launch_bounds__(256, 1) lora_gemm(float* __restrict__ out) {
    extern __shared__ char smem[];
    uint32_t sb = smem_u32(smem);
    int tid = threadIdx.x;
    int wid = tid >> 5;
    int lane = tid & 31;
    int warp_m = wid & 1;   // 2 m-blocks of 64
    int warp_n = wid >> 1;  // 4 n-blocks of 32
    int n0 = blockIdx.x * TILE_N;
    int m0 = blockIdx.y * TILE_M;

    // Per-lane ldmatrix address components (swizzle: col ^= (row&7)<<4)
    uint32_t sx   = (uint32_t)((lane & 7) << 4);
    uint32_t aOff = (uint32_t)((warp_m * 64 + (lane & 15)) * 128);
    uint32_t aSel = (uint32_t)((lane >> 4) << 4);          // 0 or 16 (k8 half)
    uint32_t bOff = (uint32_t)((warp_n * 32 + (lane & 7) + ((lane >> 4) << 3)) * 128);
    uint32_t bSel = (uint32_t)(((lane >> 3) & 1) << 4);    // 0 or 16

    float acc[4][4][4];
#pragma unroll
    for (int i = 0; i < 4; i++)
#pragma unroll
        for (int j = 0; j < 4; j++)
#pragma unroll
            for (int q = 0; q < 4; q++) acc[i][j][q] = 0.0f;

    // Prologue: stages for chunks 0..2
#pragma unroll
    for (int s = 0; s < NSTAGES - 1; s++) {
        issue_stage(sb, tid, m0, n0, s, s);
        CP_COMMIT();
    }

    for (int chunk = 0; chunk < NCHUNKS; chunk++) {
        CP_WAIT2();
        __syncthreads();

        // Prefetch chunk+3 into the stage freed by chunk-1
        int nxt = chunk + NSTAGES - 1;
        if (nxt < NCHUNKS) {
            issue_stage(sb, tid, m0, n0, nxt, nxt & (NSTAGES - 1));
        }
        CP_COMMIT();

        uint32_t sA = sb + (chunk & (NSTAGES - 1)) * STAGE_BYTES;
        uint32_t sB = sA + 16384;

#pragma unroll
        for (int s = 0; s < 2; s++) {   // two k16 steps per 32-chunk
            uint32_t Ah[4][4], Al[4][4], Bh[2][4], Bl[2][4];
            uint32_t cHi = (uint32_t)(s * 32);
            uint32_t cLo = (uint32_t)(64 + s * 32);
#pragma unroll
            for (int i = 0; i < 4; i++)
                ldsm4(Ah[i], sA + aOff + i * 2048 + ((cHi + aSel) ^ sx));
#pragma unroll
            for (int i = 0; i < 4; i++)
                ldsm4(Al[i], sA + aOff + i * 2048 + ((cLo + aSel) ^ sx));
#pragma unroll
            for (int p = 0; p < 2; p++)
                ldsm4(Bh[p], sB + bOff + p * 2048 + ((cHi + bSel) ^ sx));
#pragma unroll
            for (int p = 0; p < 2; p++)
                ldsm4(Bl[p], sB + bOff + p * 2048 + ((cLo + bSel) ^ sx));

#pragma unroll
            for (int i = 0; i < 4; i++)
#pragma unroll
                for (int j = 0; j < 4; j++)
                    mma16816(acc[i][j], Ah[i], &Bh[j >> 1][(j & 1) * 2]);
#pragma unroll
            for (int i = 0; i < 4; i++)
#pragma unroll
                for (int j = 0; j < 4; j++)
                    mma16816(acc[i][j], Ah[i], &Bl[j >> 1][(j & 1) * 2]);
#pragma unroll
            for (int i = 0; i < 4; i++)
#pragma unroll
                for (int j = 0; j < 4; j++)
                    mma16816(acc[i][j], Al[i], &Bh[j >> 1][(j & 1) * 2]);
        }
        __syncthreads();
    }

    // Epilogue: fragment layout: c0,c1 at (row t/4, col 2*(t%4)+{0,1}),
    //           c2,c3 at (row t/4 + 8, same cols)
    int r0 = m0 + warp_m * 64 + (lane >> 2);
    int c0 = n0 + warp_n * 32 + (lane & 3) * 2;
#pragma unroll
    for (int i = 0; i < 4; i++) {
#pragma unroll
        for (int j = 0; j < 4; j++) {
            float* p0 = out + (size_t)(r0 + i * 16) * N_DIM + (c0 + j * 8);
            float* p1 = out + (size_t)(r0 + i * 16 + 8) * N_DIM + (c0 + j * 8);
            float2 v0 = make_float2(acc[i][j][0], acc[i][j][1]);
            float2 v1 = make_float2(acc[i][j][2], acc[i][j][3]);
            *reinterpret_cast<float2*>(p0) = v0;
            *reinterpret_cast<float2*>(p1) = v1;
        }
    }
}

// ---------------- Launch ----------------

extern "C" void kernel_launch(void* const* d_in, const int* in_sizes, int n_in,
                              void* d_out, int out_size) {
    (void)in_sizes; (void)n_in; (void)out_size;
    const float* x       = (const float*)d_in[0];
    const float* weight  = (const float*)d_in[1];
    const float* scale_A = (const float*)d_in[2];
    const float* scale_B = (const float*)d_in[3];
    const float* g       = (const float*)d_in[4];
    const float* lora_A  = (const float*)d_in[5];
    const float* lora_B  = (const float*)d_in[6];
    float* out = (float*)d_out;

    cudaFuncSetAttribute(lora_gemm, cudaFuncAttributeMaxDynamicSharedMemorySize,
                         SMEM_TOTAL);

    precomp_x<<<(M_DIM * K_DIM) / 256, 256>>>(x);
    precomp_w<<<dim3(K_DIM / 256, N_DIM / 64), 256>>>(weight, scale_A, scale_B,
                                                      g, lora_A, lora_B);
    lora_gemm<<<dim3(N_DIM / TILE_N, M_DIM / TILE_M), 256, SMEM_TOTAL>>>(out);
}

// round 3
// speedup vs baseline: 2.2896x; 2.2896x over previous
#include <cuda_runtime.h>
#include <cuda_bf16.h>
#include <cuda_fp16.h>
#include <cstdint>

// Problem dims (fixed by the dataset)
#define M_DIM 4096   // B*S tokens
#define N_DIM 4096   // OUT
#define K_DIM 4096   // IN
#define RANK 8
#define LORA_R 16
#define LORA_SCALING_C 1.0f  // 16.0/16

#define W_SCALE 512.0f       // W packed as W*512 to keep fp16 operands in normal range
#define W_INV_SCALE (1.0f / 512.0f)

#define TILE_M 128
#define TILE_N 256
#define KCHUNK 64                  // fp16 K elements per stage = 128B per row
#define NCHUNKS (K_DIM / KCHUNK)   // 64
#define NSTAGES 4
#define STAGE_A_BYTES (TILE_M * 128)          // 16384
#define STAGE_B_BYTES (TILE_N * 128)          // 32768
#define STAGE_BYTES (STAGE_A_BYTES + STAGE_B_BYTES)   // 49152
#define SMEM_TOTAL (NSTAGES * STAGE_BYTES)    // 196608

// fp16 packed operands (x direct; W_tot * 512)
__device__ __align__(128) __half g_xh[(size_t)M_DIM * K_DIM];
__device__ __align__(128) __half g_wh[(size_t)N_DIM * K_DIM];

// ---------------- PTX helpers (sm_103 baseline ISA only) ----------------

__device__ __forceinline__ uint32_t smem_u32(const void* p) {
    uint32_t a;
    asm("{ .reg .u64 t; cvta.to.shared.u64 t, %1; cvt.u32.u64 %0, t; }"
        : "=r"(a) : "l"(p));
    return a;
}

__device__ __forceinline__ void ldsm4(uint32_t* r, uint32_t addr) {
    asm volatile("ldmatrix.sync.aligned.m8n8.x4.shared.b16 {%0,%1,%2,%3}, [%4];"
                 : "=r"(r[0]), "=r"(r[1]), "=r"(r[2]), "=r"(r[3]) : "r"(addr));
}

__device__ __forceinline__ void mma16816(float* c, const uint32_t* a,
                                         const uint32_t* b) {
    asm volatile(
        "mma.sync.aligned.m16n8k16.row.col.f32.f16.f16.f32 "
        "{%0,%1,%2,%3}, {%4,%5,%6,%7}, {%8,%9}, {%0,%1,%2,%3};"
        : "+f"(c[0]), "+f"(c[1]), "+f"(c[2]), "+f"(c[3])
        : "r"(a[0]), "r"(a[1]), "r"(a[2]), "r"(a[3]), "r"(b[0]), "r"(b[1]));
}

__device__ __forceinline__ void cp_async16(uint32_t dst, const void* src) {
    asm volatile("cp.async.cg.shared.global [%0], [%1], 16;"
                 :: "r"(dst), "l"(src));
}
#define CP_COMMIT() asm volatile("cp.async.commit_group;" ::: "memory")
#define CP_WAIT2()  asm volatile("cp.async.wait_group 2;" ::: "memory")

// ---------------- Precompute kernels ----------------

// Pack x -> fp16, contiguous [m][k]; 4 elements per thread
__global__ void precomp_x(const float* __restrict__ x) {
    int idx = blockIdx.x * 256 + threadIdx.x;   // < 4194304
    const float4 v = reinterpret_cast<const float4*>(x)[idx];
    __half2 h0 = __floats2half2_rn(v.x, v.y);
    __half2 h1 = __floats2half2_rn(v.z, v.w);
    uint2 pk;
    pk.x = *reinterpret_cast<uint32_t*>(&h0);
    pk.y = *reinterpret_cast<uint32_t*>(&h1);
    reinterpret_cast<uint2*>(g_xh)[idx] = pk;
}

// W_tot[o][i] = weight[o][i] * sum_k (scale_A[o][k]*g[k]) * scale_B[k][i]
//            + scaling * sum_r lora_B[o][r] * lora_A[r][i];   packed as fp16 * 512
__global__ void precomp_w(const float* __restrict__ weight,
                          const float* __restrict__ scale_A,
                          const float* __restrict__ scale_B,
                          const float* __restrict__ g,
                          const float* __restrict__ lora_A,
                          const float* __restrict__ lora_B) {
    __shared__ float ag[64][8];
    __shared__ float lb[64][16];
    int t = threadIdx.x;
    int i0 = blockIdx.x * 256;
    int o0 = blockIdx.y * 64;

    for (int u = t; u < 64 * 8; u += 256) {
        int ol = u >> 3, k = u & 7;
        ag[ol][k] = scale_A[(size_t)(o0 + ol) * RANK + k] * g[k];
    }
    for (int u = t; u < 64 * 16; u += 256) {
        int ol = u >> 4, r = u & 15;
        lb[ol][r] = lora_B[(size_t)(o0 + ol) * LORA_R + r] * LORA_SCALING_C;
    }
    __syncthreads();

    int i = i0 + t;
    float sb[8], la[16];
#pragma unroll
    for (int k = 0; k < 8; k++) sb[k] = scale_B[(size_t)k * K_DIM + i];
#pragma unroll
    for (int r = 0; r < 16; r++) la[r] = lora_A[(size_t)r * K_DIM + i];

#pragma unroll 4
    for (int ol = 0; ol < 64; ol++) {
        int o = o0 + ol;
        float S = 0.0f, L = 0.0f;
#pragma unroll
        for (int k = 0; k < 8; k++) S = fmaf(ag[ol][k], sb[k], S);
#pragma unroll
        for (int r = 0; r < 16; r++) L = fmaf(lb[ol][r], la[r], L);
        float w = weight[(size_t)o * K_DIM + i];
        float tot = fmaf(w, S, L) * W_SCALE;
        g_wh[(size_t)o * K_DIM + i] = __float2half_rn(tot);
    }
}

// ---------------- GEMM kernel (mma.sync fp16, single product) ----------------

__device__ __forceinline__ void issue_stage(uint32_t sb, int tid, int m0, int n0,
                                            int chunk, int stage) {
    uint32_t sA = sb + stage * STAGE_BYTES;
    uint32_t sB = sA + STAGE_A_BYTES;
    const char* xg = reinterpret_cast<const char*>(g_xh);
    const char* wg = reinterpret_cast<const char*>(g_wh);
    // A: 128 rows x 8 x 16B
#pragma unroll
    for (int p = 0; p < 4; p++) {
        int v = tid + p * 256;
        int row = v >> 3, c = v & 7;
        uint32_t dst = sA + (uint32_t)(row * 128 + ((c * 16) ^ ((row & 7) << 4)));
        const char* src = xg + ((size_t)(m0 + row) * 8192 + (size_t)chunk * 128 + c * 16);
        cp_async16(dst, src);
    }
    // B: 256 rows x 8 x 16B
#pragma unroll
    for (int p = 0; p < 8; p++) {
        int v = tid + p * 256;
        int row = v >> 3, c = v & 7;
        uint32_t dst = sB + (uint32_t)(row * 128 + ((c * 16) ^ ((row & 7) << 4)));
        const char* src = wg + ((size_t)(n0 + row) * 8192 + (size_t)chunk * 128 + c * 16);
        cp_async16(dst, src);
    }
}

__global__ void __launch_bounds__(256, 1) lora_gemm(float* __restrict__ out) {
    extern __shared__ char smem[];
    uint32_t sb = smem_u32(smem);
    int tid = threadIdx.x;
    int wid = tid >> 5;
    int lane = tid & 31;
    int warp_m = wid & 1;   // 2 m-blocks of 64
    int warp_n = wid >> 1;  // 4 n-blocks of 64
    int n0 = blockIdx.x * TILE_N;
    int m0 = blockIdx.y * TILE_M;

    // ldmatrix lane addressing (swizzle: col16 ^= (row&7)<<4)
    uint32_t sx   = (uint32_t)((lane & 7) << 4);
    uint32_t aOff = (uint32_t)((warp_m * 64 + (lane & 15)) * 128);
    uint32_t aSel = (uint32_t)((lane >> 4) << 4);          // 0 or 16
    uint32_t bOff = (uint32_t)((warp_n * 64 + (lane & 7) + ((lane >> 4) << 3)) * 128);
    uint32_t bSel = (uint32_t)(((lane >> 3) & 1) << 4);    // 0 or 16

    float acc[4][8][4];
#pragma unroll
    for (int i = 0; i < 4; i++)
#pragma unroll
        for (int j = 0; j < 8; j++)
#pragma unroll
            for (int q = 0; q < 4; q++) acc[i][j][q] = 0.0f;

    // Prologue: chunks 0..2
#pragma unroll
    for (int s = 0; s < NSTAGES - 1; s++) {
        issue_stage(sb, tid, m0, n0, s, s);
        CP_COMMIT();
    }

    for (int chunk = 0; chunk < NCHUNKS; chunk++) {
        CP_WAIT2();
        __syncthreads();

        int nxt = chunk + NSTAGES - 1;
        if (nxt < NCHUNKS) {
            issue_stage(sb, tid, m0, n0, nxt, nxt & (NSTAGES - 1));
        }
        CP_COMMIT();

        uint32_t sA = sb + (chunk & (NSTAGES - 1)) * STAGE_BYTES;
        uint32_t sB = sA + STAGE_A_BYTES;

#pragma unroll
        for (int s = 0; s < 4; s++) {   // four k16 steps per 64-chunk
            uint32_t Af[4][4], Bf[4][4];
            uint32_t cb = (uint32_t)(s * 32);
#pragma unroll
            for (int i = 0; i < 4; i++)
                ldsm4(Af[i], sA + aOff + i * 2048 + ((cb + aSel) ^ sx));
#pragma unroll
            for (int p = 0; p < 4; p++)
                ldsm4(Bf[p], sB + bOff + p * 2048 + ((cb + bSel) ^ sx));
#pragma unroll
            for (int i = 0; i < 4; i++)
#pragma unroll
                for (int j = 0; j < 8; j++)
                    mma16816(acc[i][j], Af[i], &Bf[j >> 1][(j & 1) * 2]);
        }
    }

    // Epilogue: scale by 1/512 and store.
    // Fragment: c0,c1 at (row lane/4, col 2*(lane%4)+{0,1}), c2,c3 at row+8.
    int r0 = m0 + warp_m * 64 + (lane >> 2);
    int c0 = n0 + warp_n * 64 + (lane & 3) * 2;
#pragma unroll
    for (int i = 0; i < 4; i++) {
#pragma unroll
        for (int j = 0; j < 8; j++) {
            float* p0 = out + (size_t)(r0 + i * 16) * N_DIM + (c0 + j * 8);
            float* p1 = out + (size_t)(r0 + i * 16 + 8) * N_DIM + (c0 + j * 8);
            float2 v0 = make_float2(acc[i][j][0] * W_INV_SCALE,
                                    acc[i][j][1] * W_INV_SCALE);
            float2 v1 = make_float2(acc[i][j][2] * W_INV_SCALE,
                                    acc[i][j][3] * W_INV_SCALE);
            *reinterpret_cast<float2*>(p0) = v0;
            *reinterpret_cast<float2*>(p1) = v1;
        }
    }
}

// ---------------- Launch ----------------

extern "C" void kernel_launch(void* const* d_in, const int* in_sizes, int n_in,
                              void* d_out, int out_size) {
    (void)in_sizes; (void)n_in; (void)out_size;
    const float* x       = (const float*)d_in[0];
    const float* weight  = (const float*)d_in[1];
    const float* scale_A = (const float*)d_in[2];
    const float* scale_B = (const float*)d_in[3];
    const float* g       = (const float*)d_in[4];
    const float* lora_A  = (const float*)d_in[5];
    const float* lora_B  = (const float*)d_in[6];
    float* out = (float*)d_out;

    cudaFuncSetAttribute(lora_gemm, cudaFuncAttributeMaxDynamicSharedMemorySize,
                         SMEM_TOTAL);

    precomp_x<<<(M_DIM * K_DIM / 4) / 256, 256>>>(x);
    precomp_w<<<dim3(K_DIM / 256, N_DIM / 64), 256>>>(weight, scale_A, scale_B,
                                                      g, lora_A, lora_B);
    lora_gemm<<<dim3(N_DIM / TILE_N, M_DIM / TILE_M), 256, SMEM_TOTAL>>>(out);
}

// round 4
// speedup vs baseline: 2.7745x; 1.2118x over previous
#include <cuda_runtime.h>
#include <cuda_bf16.h>
#include <cuda_fp16.h>
#include <cstdint>

// Problem dims (fixed by the dataset)
#define M_DIM 4096   // B*S tokens
#define N_DIM 4096   // OUT
#define K_DIM 4096   // IN
#define RANK 8
#define LORA_R 16
#define LORA_SCALING_C 1.0f  // 16.0/16

#define W_SCALE 512.0f       // W packed as W*512 to keep fp16 operands in normal range
#define W_INV_SCALE (1.0f / 512.0f)

#define TILE_M 128
#define TILE_N 128
#define KCHUNK 64                  // fp16 K elements per stage = 128B per row
#define NCHUNKS (K_DIM / KCHUNK)   // 64
#define NSTAGES 3
#define STAGE_A_BYTES (TILE_M * 128)          // 16384
#define STAGE_B_BYTES (TILE_N * 128)          // 16384
#define STAGE_BYTES (STAGE_A_BYTES + STAGE_B_BYTES)   // 32768
#define SMEM_TOTAL (NSTAGES * STAGE_BYTES)    // 98304 -> 2 CTAs/SM

// fp16 packed operands (x direct; W_tot * 512)
__device__ __align__(128) __half g_xh[(size_t)M_DIM * K_DIM];
__device__ __align__(128) __half g_wh[(size_t)N_DIM * K_DIM];

// ---------------- PTX helpers (sm_103 baseline ISA only) ----------------

__device__ __forceinline__ uint32_t smem_u32(const void* p) {
    uint32_t a;
    asm("{ .reg .u64 t; cvta.to.shared.u64 t, %1; cvt.u32.u64 %0, t; }"
        : "=r"(a) : "l"(p));
    return a;
}

__device__ __forceinline__ void ldsm4(uint32_t* r, uint32_t addr) {
    asm volatile("ldmatrix.sync.aligned.m8n8.x4.shared.b16 {%0,%1,%2,%3}, [%4];"
                 : "=r"(r[0]), "=r"(r[1]), "=r"(r[2]), "=r"(r[3]) : "r"(addr));
}

__device__ __forceinline__ void mma16816(float* c, const uint32_t* a,
                                         const uint32_t* b) {
    asm volatile(
        "mma.sync.aligned.m16n8k16.row.col.f32.f16.f16.f32 "
        "{%0,%1,%2,%3}, {%4,%5,%6,%7}, {%8,%9}, {%0,%1,%2,%3};"
        : "+f"(c[0]), "+f"(c[1]), "+f"(c[2]), "+f"(c[3])
        : "r"(a[0]), "r"(a[1]), "r"(a[2]), "r"(a[3]), "r"(b[0]), "r"(b[1]));
}

__device__ __forceinline__ void cp_async16(uint32_t dst, const void* src) {
    asm volatile("cp.async.cg.shared.global [%0], [%1], 16;"
                 :: "r"(dst), "l"(src));
}
#define CP_COMMIT() asm volatile("cp.async.commit_group;" ::: "memory")
#define CP_WAIT1()  asm volatile("cp.async.wait_group 1;" ::: "memory")

// ---------------- Precompute kernels ----------------

// Pack x -> fp16, contiguous [m][k]; 4 elements per thread
__global__ void precomp_x(const float* __restrict__ x) {
    int idx = blockIdx.x * 256 + threadIdx.x;   // < 4194304
    const float4 v = reinterpret_cast<const float4*>(x)[idx];
    __half2 h0 = __floats2half2_rn(v.x, v.y);
    __half2 h1 = __floats2half2_rn(v.z, v.w);
    uint2 pk;
    pk.x = *reinterpret_cast<uint32_t*>(&h0);
    pk.y = *reinterpret_cast<uint32_t*>(&h1);
    reinterpret_cast<uint2*>(g_xh)[idx] = pk;
}

// W_tot[o][i] = weight[o][i] * sum_k (scale_A[o][k]*g[k]) * scale_B[k][i]
//            + scaling * sum_r lora_B[o][r] * lora_A[r][i];   packed as fp16 * 512
__global__ void precomp_w(const float* __restrict__ weight,
                          const float* __restrict__ scale_A,
                          const float* __restrict__ scale_B,
                          const float* __restrict__ g,
                          const float* __restrict__ lora_A,
                          const float* __restrict__ lora_B) {
    __shared__ float ag[64][8];
    __shared__ float lb[64][16];
    int t = threadIdx.x;
    int i0 = blockIdx.x * 256;
    int o0 = blockIdx.y * 64;

    for (int u = t; u < 64 * 8; u += 256) {
        int ol = u >> 3, k = u & 7;
        ag[ol][k] = scale_A[(size_t)(o0 + ol) * RANK + k] * g[k];
    }
    for (int u = t; u < 64 * 16; u += 256) {
        int ol = u >> 4, r = u & 15;
        lb[ol][r] = lora_B[(size_t)(o0 + ol) * LORA_R + r] * LORA_SCALING_C;
    }
    __syncthreads();

    int i = i0 + t;
    float sb[8], la[16];
#pragma unroll
    for (int k = 0; k < 8; k++) sb[k] = scale_B[(size_t)k * K_DIM + i];
#pragma unroll
    for (int r = 0; r < 16; r++) la[r] = lora_A[(size_t)r * K_DIM + i];

#pragma unroll 4
    for (int ol = 0; ol < 64; ol++) {
        int o = o0 + ol;
        float S = 0.0f, L = 0.0f;
#pragma unroll
        for (int k = 0; k < 8; k++) S = fmaf(ag[ol][k], sb[k], S);
#pragma unroll
        for (int r = 0; r < 16; r++) L = fmaf(lb[ol][r], la[r], L);
        float w = weight[(size_t)o * K_DIM + i];
        float tot = fmaf(w, S, L) * W_SCALE;
        g_wh[(size_t)o * K_DIM + i] = __float2half_rn(tot);
    }
}

// ---------------- GEMM kernel (mma.sync fp16, single product) ----------------

__device__ __forceinline__ void issue_stage(uint32_t sb, int tid, int m0, int n0,
                                            int chunk, int stage) {
    uint32_t sA = sb + stage * STAGE_BYTES;
    uint32_t sB = sA + STAGE_A_BYTES;
    const char* xg = reinterpret_cast<const char*>(g_xh);
    const char* wg = reinterpret_cast<const char*>(g_wh);
    // A: 128 rows x 8 x 16B
#pragma unroll
    for (int p = 0; p < 4; p++) {
        int v = tid + p * 256;
        int row = v >> 3, c = v & 7;
        uint32_t dst = sA + (uint32_t)(row * 128 + ((c * 16) ^ ((row & 7) << 4)));
        const char* src = xg + ((size_t)(m0 + row) * 8192 + (size_t)chunk * 128 + c * 16);
        cp_async16(dst, src);
    }
    // B: 128 rows x 8 x 16B
#pragma unroll
    for (int p = 0; p < 4; p++) {
        int v = tid + p * 256;
        int row = v >> 3, c = v & 7;
        uint32_t dst = sB + (uint32_t)(row * 128 + ((c * 16) ^ ((row & 7) << 4)));
        const char* src = wg + ((size_t)(n0 + row) * 8192 + (size_t)chunk * 128 + c * 16);
        cp_async16(dst, src);
    }
}

__global__ void __launch_bounds__(256, 2) lora_gemm(float* __restrict__ out) {
    extern __shared__ char smem[];
    uint32_t sb = smem_u32(smem);
    int tid = threadIdx.x;
    int wid = tid >> 5;
    int lane = tid & 31;
    int warp_m = wid & 1;   // 2 m-blocks of 64
    int warp_n = wid >> 1;  // 4 n-blocks of 32
    int n0 = blockIdx.x * TILE_N;
    int m0 = blockIdx.y * TILE_M;

    // ldmatrix lane addressing (swizzle: col16 ^= (row&7)<<4)
    uint32_t sx   = (uint32_t)((lane & 7) << 4);
    uint32_t aOff = (uint32_t)((warp_m * 64 + (lane & 15)) * 128);
    uint32_t aSel = (uint32_t)((lane >> 4) << 4);          // 0 or 16
    uint32_t bOff = (uint32_t)((warp_n * 32 + (lane & 7) + ((lane >> 4) << 3)) * 128);
    uint32_t bSel = (uint32_t)(((lane >> 3) & 1) << 4);    // 0 or 16

    float acc[4][4][4];
#pragma unroll
    for (int i = 0; i < 4; i++)
#pragma unroll
        for (int j = 0; j < 4; j++)
#pragma unroll
            for (int q = 0; q < 4; q++) acc[i][j][q] = 0.0f;

    // Prologue: chunks 0,1 into stages 0,1
#pragma unroll
    for (int s = 0; s < NSTAGES - 1; s++) {
        issue_stage(sb, tid, m0, n0, s, s);
        CP_COMMIT();
    }

    int stage = 0;
    for (int chunk = 0; chunk < NCHUNKS; chunk++) {
        CP_WAIT1();            // chunk's group complete (<=1 outstanding)
        __syncthreads();       // also guards reuse of stage (chunk-1)

        int nxt = chunk + NSTAGES - 1;
        int nstage = stage + (NSTAGES - 1);
        if (nstage >= NSTAGES) nstage -= NSTAGES;
        if (nxt < NCHUNKS) {
            issue_stage(sb, tid, m0, n0, nxt, nstage);
        }
        CP_COMMIT();

        uint32_t sA = sb + stage * STAGE_BYTES;
        uint32_t sB = sA + STAGE_A_BYTES;

#pragma unroll
        for (int s = 0; s < 4; s++) {   // four k16 steps per 64-chunk
            uint32_t Af[4][4], Bf[2][4];
            uint32_t cb = (uint32_t)(s * 32);
#pragma unroll
            for (int i = 0; i < 4; i++)
                ldsm4(Af[i], sA + aOff + i * 2048 + ((cb + aSel) ^ sx));
#pragma unroll
            for (int p = 0; p < 2; p++)
                ldsm4(Bf[p], sB + bOff + p * 2048 + ((cb + bSel) ^ sx));
#pragma unroll
            for (int i = 0; i < 4; i++)
#pragma unroll
                for (int j = 0; j < 4; j++)
                    mma16816(acc[i][j], Af[i], &Bf[j >> 1][(j & 1) * 2]);
        }

        if (++stage == NSTAGES) stage = 0;
    }

    // Epilogue: scale by 1/512 and store.
    // Fragment: c0,c1 at (row lane/4, col 2*(lane%4)+{0,1}), c2,c3 at row+8.
    int r0 = m0 + warp_m * 64 + (lane >> 2);
    int c0 = n0 + warp_n * 32 + (lane & 3) * 2;
#pragma unroll
    for (int i = 0; i < 4; i++) {
#pragma unroll
        for (int j = 0; j < 4; j++) {
            float* p0 = out + (size_t)(r0 + i * 16) * N_DIM + (c0 + j * 8);
            float* p1 = out + (size_t)(r0 + i * 16 + 8) * N_DIM + (c0 + j * 8);
            float2 v0 = make_float2(acc[i][j][0] * W_INV_SCALE,
                                    acc[i][j][1] * W_INV_SCALE);
            float2 v1 = make_float2(acc[i][j][2] * W_INV_SCALE,
                                    acc[i][j][3] * W_INV_SCALE);
            *reinterpret_cast<float2*>(p0) = v0;
            *reinterpret_cast<float2*>(p1) = v1;
        }
    }
}

// ---------------- Launch ----------------

extern "C" void kernel_launch(void* const* d_in, const int* in_sizes, int n_in,
                              void* d_out, int out_size) {
    (void)in_sizes; (void)n_in; (void)out_size;
    const float* x       = (const float*)d_in[0];
    const float* weight  = (const float*)d_in[1];
    const float* scale_A = (const float*)d_in[2];
    const float* scale_B = (const float*)d_in[3];
    const float* g       = (const float*)d_in[4];
    const float* lora_A  = (const float*)d_in[5];
    const float* lora_B  = (const float*)d_in[6];
    float* out = (float*)d_out;

    cudaFuncSetAttribute(lora_gemm, cudaFuncAttributeMaxDynamicSharedMemorySize,
                         SMEM_TOTAL);

    precomp_x<<<(M_DIM * K_DIM / 4) / 256, 256>>>(x);
    precomp_w<<<dim3(K_DIM / 256, N_DIM / 64), 256>>>(weight, scale_A, scale_B,
                                                      g, lora_A, lora_B);
    lora_gemm<<<dim3(N_DIM / TILE_N, M_DIM / TILE_M), 256, SMEM_TOTAL>>>(out);
}